// round 13
// baseline (speedup 1.0000x reference)
#include <cuda_runtime.h>
#include <cuda_bf16.h>
#include <mma.h>
#include <cstdint>

using namespace nvcuda;

// Problem dims
#define NB    8
#define NMAT  256
#define N3    64
#define NF    33
#define NPLANE (NMAT * NMAT)       // 65536
#define NTUBES (NB * NPLANE)       // 524288
#define NFP    (NB * NF)           // 264

#define APLANE (256 * 512)
#define BPLANE (512 * 512)

// Scratch
__device__ static __nv_bfloat16 g_Ah[(size_t)NFP * APLANE];
__device__ static __nv_bfloat16 g_Al[(size_t)NFP * APLANE];
__device__ static __nv_bfloat16 g_Bh[(size_t)NFP * BPLANE];
__device__ static __nv_bfloat16 g_Bl[(size_t)NFP * BPLANE];
__device__ static float2       g_Cf[(size_t)NFP * NPLANE];

// ---------------------------------------------------------------------------
// Compile-time twiddles (device-qualified)
// ---------------------------------------------------------------------------
__device__ constexpr float TW32R[16] = {
    1.0f, 0.980785280403230449f, 0.923879532511286756f, 0.831469612302545237f,
    0.707106781186547524f, 0.555570233019602225f, 0.382683432365089772f,
    0.195090322016128268f, 0.0f, -0.195090322016128268f, -0.382683432365089772f,
    -0.555570233019602225f, -0.707106781186547524f, -0.831469612302545237f,
    -0.923879532511286756f, -0.980785280403230449f };
__device__ constexpr float TW32I[16] = {
    0.0f, 0.195090322016128268f, 0.382683432365089772f, 0.555570233019602225f,
    0.707106781186547524f, 0.831469612302545237f, 0.923879532511286756f,
    0.980785280403230449f, 1.0f, 0.980785280403230449f, 0.923879532511286756f,
    0.831469612302545237f, 0.707106781186547524f, 0.555570233019602225f,
    0.382683432365089772f, 0.195090322016128268f };
__device__ constexpr float W64R[33] = {
    1.0f, 0.995184726672196886f, 0.980785280403230449f, 0.956940335732208865f,
    0.923879532511286756f, 0.881921264348355030f, 0.831469612302545237f,
    0.773010453362736961f, 0.707106781186547524f, 0.634393284163645498f,
    0.555570233019602225f, 0.471396736825997649f, 0.382683432365089772f,
    0.290284677254462368f, 0.195090322016128268f, 0.098017140329560602f,
    0.0f, -0.098017140329560602f, -0.195090322016128268f, -0.290284677254462368f,
    -0.382683432365089772f, -0.471396736825997649f, -0.555570233019602225f,
    -0.634393284163645498f, -0.707106781186547524f, -0.773010453362736961f,
    -0.831469612302545237f, -0.881921264348355030f, -0.923879532511286756f,
    -0.956940335732208865f, -0.980785280403230449f, -0.995184726672196886f, -1.0f };
__device__ constexpr float W64I[33] = {
    0.0f, 0.098017140329560602f, 0.195090322016128268f, 0.290284677254462368f,
    0.382683432365089772f, 0.471396736825997649f, 0.555570233019602225f,
    0.634393284163645498f, 0.707106781186547524f, 0.773010453362736961f,
    0.831469612302545237f, 0.881921264348355030f, 0.923879532511286756f,
    0.956940335732208865f, 0.980785280403230449f, 0.995184726672196886f,
    1.0f, 0.995184726672196886f, 0.980785280403230449f, 0.956940335732208865f,
    0.923879532511286756f, 0.881921264348355030f, 0.831469612302545237f,
    0.773010453362736961f, 0.707106781186547524f, 0.634393284163645498f,
    0.555570233019602225f, 0.471396736825997649f, 0.382683432365089772f,
    0.290284677254462368f, 0.195090322016128268f, 0.098017140329560602f, 0.0f };
__device__ constexpr int BR5[32] = {
    0,16,8,24,4,20,12,28,2,18,10,26,6,22,14,30,
    1,17,9,25,5,21,13,29,3,19,11,27,7,23,15,31 };

// 32-point DIF FFT, natural in, bit-reversed out. SIGN=+1 inverse, -1 forward.
template<int M, int SIGN>
static __device__ __forceinline__ void fft32_stage(float* zr, float* zi) {
    constexpr int H = M / 2;
#pragma unroll
    for (int g = 0; g < 32; g += M)
#pragma unroll
        for (int j = 0; j < H; ++j) {
            const float wr = TW32R[j * (32 / M)];
            const float wi = SIGN * TW32I[j * (32 / M)];
            const int i0 = g + j, i1 = g + j + H;
            const float ar = zr[i0], ai = zi[i0];
            const float br_ = zr[i1], bi = zi[i1];
            zr[i0] = ar + br_;  zi[i0] = ai + bi;
            const float dr = ar - br_, di = ai - bi;
            zr[i1] = dr * wr - di * wi;
            zi[i1] = dr * wi + di * wr;
        }
}
template<int SIGN>
static __device__ __forceinline__ void fft32(float* zr, float* zi) {
    fft32_stage<32, SIGN>(zr, zi);
    fft32_stage<16, SIGN>(zr, zi);
    fft32_stage<8,  SIGN>(zr, zi);
    fft32_stage<4,  SIGN>(zr, zi);
    fft32_stage<2,  SIGN>(zr, zi);
}

static __device__ __forceinline__ uint32_t pack2(__nv_bfloat16 a, __nv_bfloat16 b) {
    __nv_bfloat162 t; t.x = a; t.y = b;
    return *reinterpret_cast<uint32_t*>(&t);
}

// ===========================================================================
// Forward rfft64 (k=0..32) via complex FFT32, fused bf16 hi/lo split + pack.
// ===========================================================================
__global__ __launch_bounds__(128) void fft_fwd_kernel(const float* __restrict__ x, int sel)
{
    __shared__ float sx[128][N3 + 1];
    const int tid = threadIdx.x;

    const float* src = x + (size_t)blockIdx.x * 128 * N3;
    for (int i = tid; i < 128 * N3; i += 128)
        sx[i >> 6][i & 63] = src[i];
    __syncthreads();

    float zr[32], zi[32];
#pragma unroll
    for (int n = 0; n < 32; ++n) {
        zr[n] = sx[tid][2 * n];
        zi[n] = sx[tid][2 * n + 1];
    }
    fft32<-1>(zr, zi);   // forward; output bit-reversed

    const int tube = blockIdx.x * 128 + tid;
    const int b = tube >> 16;
    const int i = (tube >> 8) & 255;
    const int j = tube & 255;

#pragma unroll
    for (int k = 0; k <= 32; ++k) {
        float Xr, Xi;
        if (k == 0 || k == 32) {
            const float e = zr[0], o = zi[0];
            Xr = (k == 0) ? (e + o) : (e - o);
            Xi = 0.0f;
        } else {
            const float Zkr = zr[BR5[k]],             Zki = zi[BR5[k]];
            const float Zcr = zr[BR5[(32 - k) & 31]], Zci = -zi[BR5[(32 - k) & 31]];
            const float Er = 0.5f * (Zkr + Zcr), Ei = 0.5f * (Zki + Zci);
            const float Dr = 0.5f * (Zkr - Zcr), Di = 0.5f * (Zki - Zci);
            const float Or = Di, Oi = -Dr;
            Xr = Er + W64R[k] * Or + W64I[k] * Oi;
            Xi = Ei + W64R[k] * Oi - W64I[k] * Or;
        }

        const int p = b * NF + k;
        const __nv_bfloat16 rh = __float2bfloat16(Xr);
        const __nv_bfloat16 ih = __float2bfloat16(Xi);
        const __nv_bfloat16 rl = __float2bfloat16(Xr - __bfloat162float(rh));
        const __nv_bfloat16 il = __float2bfloat16(Xi - __bfloat162float(ih));

        if (sel == 0) {
            const size_t off = (size_t)p * APLANE + (size_t)i * 512 + 2 * j;
            *reinterpret_cast<uint32_t*>(g_Ah + off) = pack2(rh, ih);
            *reinterpret_cast<uint32_t*>(g_Al + off) = pack2(rl, il);
        } else {
            const size_t o0 = (size_t)p * BPLANE + (size_t)(2 * i) * 512 + 2 * j;
            const size_t o1 = o0 + 512;
            *reinterpret_cast<uint32_t*>(g_Bh + o0) = pack2(rh, ih);
            *reinterpret_cast<uint32_t*>(g_Bh + o1) = pack2(__hneg(ih), rh);
            *reinterpret_cast<uint32_t*>(g_Bl + o0) = pack2(rl, il);
            *reinterpret_cast<uint32_t*>(g_Bl + o1) = pack2(__hneg(il), rl);
        }
    }
}

// ===========================================================================
// Batched bf16 wmma GEMM with cp.async double buffering.
// Grid: (2 m-tiles, 4 n-tiles, 264 planes) — plane SLOWEST so the 8 CTAs of a
// plane are adjacent in schedule order and share its 1.5 MB operands via L2.
// ===========================================================================
#define CP_ASYNC16(dst, src) \
    asm volatile("cp.async.cg.shared.global [%0], [%1], 16;" :: "r"(dst), "l"(src) : "memory")
#define CP_COMMIT() asm volatile("cp.async.commit_group;" ::: "memory")
#define CP_WAIT1()  asm volatile("cp.async.wait_group 1;" ::: "memory")
#define CP_WAIT0()  asm volatile("cp.async.wait_group 0;" ::: "memory")

__global__ __launch_bounds__(256, 2) void cgemm_wmma_kernel()
{
    __shared__ __nv_bfloat16 Ah[2][128][24], Al[2][128][24];
    __shared__ __nv_bfloat16 Bh[2][16][136], Bl[2][16][136];

    const int p  = blockIdx.z;
    const int m0 = blockIdx.x * 128;
    const int n0 = blockIdx.y * 128;

    const __nv_bfloat16* __restrict__ Abh = g_Ah + (size_t)p * APLANE + (size_t)m0 * 512;
    const __nv_bfloat16* __restrict__ Abl = g_Al + (size_t)p * APLANE + (size_t)m0 * 512;
    const __nv_bfloat16* __restrict__ Bbh = g_Bh + (size_t)p * BPLANE + n0;
    const __nv_bfloat16* __restrict__ Bbl = g_Bl + (size_t)p * BPLANE + n0;
    float* __restrict__ Cp = reinterpret_cast<float*>(g_Cf)
                           + (size_t)p * (256 * 512) + (size_t)m0 * 512 + n0;

    const int tid = threadIdx.x;
    const int wid = tid >> 5;
    const int wm  = wid & 1;
    const int wn  = wid >> 1;

    const int ar = tid >> 1;
    const int ac = (tid & 1) * 8;
    const int br = tid >> 4;
    const int bc = (tid & 15) * 8;

    const uint32_t sAh = (uint32_t)__cvta_generic_to_shared(&Ah[0][ar][ac]);
    const uint32_t sAl = (uint32_t)__cvta_generic_to_shared(&Al[0][ar][ac]);
    const uint32_t sBh = (uint32_t)__cvta_generic_to_shared(&Bh[0][br][bc]);
    const uint32_t sBl = (uint32_t)__cvta_generic_to_shared(&Bl[0][br][bc]);
    const uint32_t stA = 128 * 24 * 2;
    const uint32_t stB = 16 * 136 * 2;

    const __nv_bfloat16* gAh = Abh + (size_t)ar * 512 + ac;
    const __nv_bfloat16* gAl = Abl + (size_t)ar * 512 + ac;
    const __nv_bfloat16* gBh = Bbh + (size_t)br * 512 + bc;
    const __nv_bfloat16* gBl = Bbl + (size_t)br * 512 + bc;

#define LOAD_CHUNK(st, c) do {                                  \
        const int _k0 = (c) * 16;                               \
        CP_ASYNC16(sAh + (st) * stA, gAh + _k0);                \
        CP_ASYNC16(sAl + (st) * stA, gAl + _k0);                \
        CP_ASYNC16(sBh + (st) * stB, gBh + (size_t)_k0 * 512);  \
        CP_ASYNC16(sBl + (st) * stB, gBl + (size_t)_k0 * 512);  \
        CP_COMMIT();                                            \
    } while (0)

    wmma::fragment<wmma::accumulator, 16, 16, 16, float> acc[4][2];
#pragma unroll
    for (int fm = 0; fm < 4; ++fm)
#pragma unroll
        for (int fn = 0; fn < 2; ++fn)
            wmma::fill_fragment(acc[fm][fn], 0.0f);

    LOAD_CHUNK(0, 0);
    LOAD_CHUNK(1, 1);

    for (int c = 0; c < 32; ++c) {
        const int st = c & 1;
        if (c == 31) { CP_WAIT0(); } else { CP_WAIT1(); }
        __syncthreads();

        wmma::fragment<wmma::matrix_b, 16, 16, 16, __nv_bfloat16, wmma::row_major> fbh[2], fbl[2];
#pragma unroll
        for (int fn = 0; fn < 2; ++fn) {
            wmma::load_matrix_sync(fbh[fn], &Bh[st][0][wn * 32 + fn * 16], 136);
            wmma::load_matrix_sync(fbl[fn], &Bl[st][0][wn * 32 + fn * 16], 136);
        }
#pragma unroll
        for (int fm = 0; fm < 4; ++fm) {
            wmma::fragment<wmma::matrix_a, 16, 16, 16, __nv_bfloat16, wmma::row_major> fah, fal;
            wmma::load_matrix_sync(fah, &Ah[st][wm * 64 + fm * 16][0], 24);
            wmma::load_matrix_sync(fal, &Al[st][wm * 64 + fm * 16][0], 24);
#pragma unroll
            for (int fn = 0; fn < 2; ++fn) {
                wmma::mma_sync(acc[fm][fn], fah, fbh[fn], acc[fm][fn]);
                wmma::mma_sync(acc[fm][fn], fah, fbl[fn], acc[fm][fn]);
                wmma::mma_sync(acc[fm][fn], fal, fbh[fn], acc[fm][fn]);
            }
        }
        __syncthreads();
        if (c + 2 < 32) LOAD_CHUNK(st, c + 2);
    }

#pragma unroll
    for (int fm = 0; fm < 4; ++fm)
#pragma unroll
        for (int fn = 0; fn < 2; ++fn)
            wmma::store_matrix_sync(Cp + (size_t)(wm * 64 + fm * 16) * 512 + wn * 32 + fn * 16,
                                    acc[fm][fn], 512, wmma::mem_row_major);
}

// ===========================================================================
// Inverse: Hermitian spectrum -> real 64, via complex iFFT32 in registers.
// ===========================================================================
__global__ __launch_bounds__(256) void ifft_kernel(float* __restrict__ out)
{
    const int tube = blockIdx.x * 256 + threadIdx.x;
    const int b    = tube >> 16;
    const int in_  = tube & 0xFFFF;

    float zr[32], zi[32];
    const float h = 1.0f / 64.0f;

    {
        const float2 X0  = g_Cf[((size_t)(b * NF + 0)  << 16) + in_];
        const float2 X32 = g_Cf[((size_t)(b * NF + 32) << 16) + in_];
        const float Er = (X0.x + X32.x) * h, Ei = (X0.y + X32.y) * h;
        const float Or = (X0.x - X32.x) * h, Oi = (X0.y - X32.y) * h;
        zr[0] = Er - Oi;
        zi[0] = Ei + Or;
    }
#pragma unroll
    for (int k = 1; k <= 16; ++k) {
        const float2 Xk = g_Cf[((size_t)(b * NF + k)        << 16) + in_];
        const float2 Xq = g_Cf[((size_t)(b * NF + (32 - k)) << 16) + in_];
        const float Er = (Xk.x + Xq.x) * h, Ei = (Xk.y - Xq.y) * h;
        const float Dr = (Xk.x - Xq.x) * h, Di = (Xk.y + Xq.y) * h;
        const float Or = Dr * W64R[k] - Di * W64I[k];
        const float Oi = Dr * W64I[k] + Di * W64R[k];
        zr[k] = Er - Oi;
        zi[k] = Ei + Or;
        if (k < 16) {
            zr[32 - k] = Er + Oi;
            zi[32 - k] = Or - Ei;
        }
    }

    fft32<1>(zr, zi);

    float* dst = out + (size_t)tube * N3;
#pragma unroll
    for (int n = 0; n < 32; n += 2) {
        const int p0 = BR5[n], p1 = BR5[n + 1];
        *reinterpret_cast<float4*>(dst + 2 * n) =
            make_float4(zr[p0], zi[p0], zr[p1], zi[p1]);
    }
}

// ===========================================================================
extern "C" void kernel_launch(void* const* d_in, const int* in_sizes, int n_in,
                              void* d_out, int out_size)
{
    const float* A = (const float*)d_in[0];
    const float* B = (const float*)d_in[1];
    float* out = (float*)d_out;

    const int fftBlocks = NTUBES / 128;          // 4096
    fft_fwd_kernel<<<fftBlocks, 128>>>(A, 0);
    fft_fwd_kernel<<<fftBlocks, 128>>>(B, 1);

    dim3 ggrid(2, 4, NFP);                       // plane = z (slowest)
    cgemm_wmma_kernel<<<ggrid, 256>>>();

    ifft_kernel<<<NTUBES / 256, 256>>>(out);
}

// round 14
// speedup vs baseline: 1.0329x; 1.0329x over previous
#include <cuda_runtime.h>
#include <cuda_bf16.h>
#include <mma.h>
#include <cstdint>

using namespace nvcuda;

// Problem dims
#define NB    8
#define NMAT  256
#define N3    64
#define NF    33
#define NPLANE (NMAT * NMAT)       // 65536
#define NTUBES (NB * NPLANE)       // 524288
#define NFP    (NB * NF)           // 264

#define APLANE (256 * 512)
#define BPLANE (512 * 512)

// Scratch
__device__ static __nv_bfloat16 g_Ah[(size_t)NFP * APLANE];
__device__ static __nv_bfloat16 g_Al[(size_t)NFP * APLANE];
__device__ static __nv_bfloat16 g_Bh[(size_t)NFP * BPLANE];
__device__ static __nv_bfloat16 g_Bl[(size_t)NFP * BPLANE];
__device__ static float2       g_Cf[(size_t)NFP * NPLANE];

// ---------------------------------------------------------------------------
// Compile-time twiddles (device-qualified)
// ---------------------------------------------------------------------------
__device__ constexpr float TW32R[16] = {
    1.0f, 0.980785280403230449f, 0.923879532511286756f, 0.831469612302545237f,
    0.707106781186547524f, 0.555570233019602225f, 0.382683432365089772f,
    0.195090322016128268f, 0.0f, -0.195090322016128268f, -0.382683432365089772f,
    -0.555570233019602225f, -0.707106781186547524f, -0.831469612302545237f,
    -0.923879532511286756f, -0.980785280403230449f };
__device__ constexpr float TW32I[16] = {
    0.0f, 0.195090322016128268f, 0.382683432365089772f, 0.555570233019602225f,
    0.707106781186547524f, 0.831469612302545237f, 0.923879532511286756f,
    0.980785280403230449f, 1.0f, 0.980785280403230449f, 0.923879532511286756f,
    0.831469612302545237f, 0.707106781186547524f, 0.555570233019602225f,
    0.382683432365089772f, 0.195090322016128268f };
__device__ constexpr float W64R[33] = {
    1.0f, 0.995184726672196886f, 0.980785280403230449f, 0.956940335732208865f,
    0.923879532511286756f, 0.881921264348355030f, 0.831469612302545237f,
    0.773010453362736961f, 0.707106781186547524f, 0.634393284163645498f,
    0.555570233019602225f, 0.471396736825997649f, 0.382683432365089772f,
    0.290284677254462368f, 0.195090322016128268f, 0.098017140329560602f,
    0.0f, -0.098017140329560602f, -0.195090322016128268f, -0.290284677254462368f,
    -0.382683432365089772f, -0.471396736825997649f, -0.555570233019602225f,
    -0.634393284163645498f, -0.707106781186547524f, -0.773010453362736961f,
    -0.831469612302545237f, -0.881921264348355030f, -0.923879532511286756f,
    -0.956940335732208865f, -0.980785280403230449f, -0.995184726672196886f, -1.0f };
__device__ constexpr float W64I[33] = {
    0.0f, 0.098017140329560602f, 0.195090322016128268f, 0.290284677254462368f,
    0.382683432365089772f, 0.471396736825997649f, 0.555570233019602225f,
    0.634393284163645498f, 0.707106781186547524f, 0.773010453362736961f,
    0.831469612302545237f, 0.881921264348355030f, 0.923879532511286756f,
    0.956940335732208865f, 0.980785280403230449f, 0.995184726672196886f,
    1.0f, 0.995184726672196886f, 0.980785280403230449f, 0.956940335732208865f,
    0.923879532511286756f, 0.881921264348355030f, 0.831469612302545237f,
    0.773010453362736961f, 0.707106781186547524f, 0.634393284163645498f,
    0.555570233019602225f, 0.471396736825997649f, 0.382683432365089772f,
    0.290284677254462368f, 0.195090322016128268f, 0.098017140329560602f, 0.0f };
__device__ constexpr int BR5[32] = {
    0,16,8,24,4,20,12,28,2,18,10,26,6,22,14,30,
    1,17,9,25,5,21,13,29,3,19,11,27,7,23,15,31 };

// 32-point DIF FFT, natural in, bit-reversed out. SIGN=+1 inverse, -1 forward.
template<int M, int SIGN>
static __device__ __forceinline__ void fft32_stage(float* zr, float* zi) {
    constexpr int H = M / 2;
#pragma unroll
    for (int g = 0; g < 32; g += M)
#pragma unroll
        for (int j = 0; j < H; ++j) {
            const float wr = TW32R[j * (32 / M)];
            const float wi = SIGN * TW32I[j * (32 / M)];
            const int i0 = g + j, i1 = g + j + H;
            const float ar = zr[i0], ai = zi[i0];
            const float br_ = zr[i1], bi = zi[i1];
            zr[i0] = ar + br_;  zi[i0] = ai + bi;
            const float dr = ar - br_, di = ai - bi;
            zr[i1] = dr * wr - di * wi;
            zi[i1] = dr * wi + di * wr;
        }
}
template<int SIGN>
static __device__ __forceinline__ void fft32(float* zr, float* zi) {
    fft32_stage<32, SIGN>(zr, zi);
    fft32_stage<16, SIGN>(zr, zi);
    fft32_stage<8,  SIGN>(zr, zi);
    fft32_stage<4,  SIGN>(zr, zi);
    fft32_stage<2,  SIGN>(zr, zi);
}

static __device__ __forceinline__ uint32_t pack2(__nv_bfloat16 a, __nv_bfloat16 b) {
    __nv_bfloat162 t; t.x = a; t.y = b;
    return *reinterpret_cast<uint32_t*>(&t);
}

// ===========================================================================
// Forward rfft64 (k=0..32) via complex FFT32, fused bf16 hi/lo split + pack.
// ===========================================================================
__global__ __launch_bounds__(128) void fft_fwd_kernel(const float* __restrict__ x, int sel)
{
    __shared__ float sx[128][N3 + 1];
    const int tid = threadIdx.x;

    const float* src = x + (size_t)blockIdx.x * 128 * N3;
    for (int i = tid; i < 128 * N3; i += 128)
        sx[i >> 6][i & 63] = src[i];
    __syncthreads();

    float zr[32], zi[32];
#pragma unroll
    for (int n = 0; n < 32; ++n) {
        zr[n] = sx[tid][2 * n];
        zi[n] = sx[tid][2 * n + 1];
    }
    fft32<-1>(zr, zi);   // forward; output bit-reversed

    const int tube = blockIdx.x * 128 + tid;
    const int b = tube >> 16;
    const int i = (tube >> 8) & 255;
    const int j = tube & 255;

#pragma unroll
    for (int k = 0; k <= 32; ++k) {
        float Xr, Xi;
        if (k == 0 || k == 32) {
            const float e = zr[0], o = zi[0];
            Xr = (k == 0) ? (e + o) : (e - o);
            Xi = 0.0f;
        } else {
            const float Zkr = zr[BR5[k]],             Zki = zi[BR5[k]];
            const float Zcr = zr[BR5[(32 - k) & 31]], Zci = -zi[BR5[(32 - k) & 31]];
            const float Er = 0.5f * (Zkr + Zcr), Ei = 0.5f * (Zki + Zci);
            const float Dr = 0.5f * (Zkr - Zcr), Di = 0.5f * (Zki - Zci);
            const float Or = Di, Oi = -Dr;
            Xr = Er + W64R[k] * Or + W64I[k] * Oi;
            Xi = Ei + W64R[k] * Oi - W64I[k] * Or;
        }

        const int p = b * NF + k;
        const __nv_bfloat16 rh = __float2bfloat16(Xr);
        const __nv_bfloat16 ih = __float2bfloat16(Xi);
        const __nv_bfloat16 rl = __float2bfloat16(Xr - __bfloat162float(rh));
        const __nv_bfloat16 il = __float2bfloat16(Xi - __bfloat162float(ih));

        if (sel == 0) {
            const size_t off = (size_t)p * APLANE + (size_t)i * 512 + 2 * j;
            *reinterpret_cast<uint32_t*>(g_Ah + off) = pack2(rh, ih);
            *reinterpret_cast<uint32_t*>(g_Al + off) = pack2(rl, il);
        } else {
            const size_t o0 = (size_t)p * BPLANE + (size_t)(2 * i) * 512 + 2 * j;
            const size_t o1 = o0 + 512;
            *reinterpret_cast<uint32_t*>(g_Bh + o0) = pack2(rh, ih);
            *reinterpret_cast<uint32_t*>(g_Bh + o1) = pack2(__hneg(ih), rh);
            *reinterpret_cast<uint32_t*>(g_Bl + o0) = pack2(rl, il);
            *reinterpret_cast<uint32_t*>(g_Bl + o1) = pack2(__hneg(il), rl);
        }
    }
}

// ===========================================================================
// Batched bf16 wmma GEMM: CTA tile 128(m) x 256(n'), 512 threads, 16 warps
// @ 64x32 warp tiles. 3-stage cp.async pipeline, ONE __syncthreads per chunk.
// ===========================================================================
#define CP_ASYNC16(dst, src) \
    asm volatile("cp.async.cg.shared.global [%0], [%1], 16;" :: "r"(dst), "l"(src) : "memory")
#define CP_COMMIT() asm volatile("cp.async.commit_group;" ::: "memory")
#define CP_WAIT1()  asm volatile("cp.async.wait_group 1;" ::: "memory")
#define CP_WAIT0()  asm volatile("cp.async.wait_group 0;" ::: "memory")

#define STG_BYTES 29184            // per-stage: Ah 6144 + Al 6144 + Bh 8448 + Bl 8448
#define OF_AL 6144
#define OF_BH 12288
#define OF_BL 20736
#define SMEM_GEMM (3 * STG_BYTES)  // 87552

__global__ __launch_bounds__(512) void cgemm_wmma_kernel()
{
    extern __shared__ char sm[];

    const int p  = blockIdx.z;
    const int m0 = blockIdx.x * 128;
    const int n0 = blockIdx.y * 256;

    const __nv_bfloat16* __restrict__ Abh = g_Ah + (size_t)p * APLANE + (size_t)m0 * 512;
    const __nv_bfloat16* __restrict__ Abl = g_Al + (size_t)p * APLANE + (size_t)m0 * 512;
    const __nv_bfloat16* __restrict__ Bbh = g_Bh + (size_t)p * BPLANE + n0;
    const __nv_bfloat16* __restrict__ Bbl = g_Bl + (size_t)p * BPLANE + n0;
    float* __restrict__ Cp = reinterpret_cast<float*>(g_Cf)
                           + (size_t)p * (256 * 512) + (size_t)m0 * 512 + n0;

    const int tid = threadIdx.x;
    const int wid = tid >> 5;
    const int wm  = wid & 1;        // 2 m-halves of 64 rows
    const int wn  = wid >> 1;       // 8 n-slots of 32 n'-cols

    // ---- cp.async mapping: each thread issues 1 A op + 2 B ops (16B each)
    const int aSel = tid >> 8;              // 0 -> Ah, 1 -> Al
    const int ao   = tid & 255;
    const int ar   = ao >> 1;               // 0..127
    const int ac   = (ao & 1) * 8;          // 0 or 8
    const int br   = tid >> 5;              // 0..15
    const int bc   = (tid & 31) * 8;        // 0..248

    const __nv_bfloat16* gA  = (aSel ? Abl : Abh) + (size_t)ar * 512 + ac;
    const __nv_bfloat16* gBh = Bbh + (size_t)br * 512 + bc;
    const __nv_bfloat16* gBl = Bbl + (size_t)br * 512 + bc;

    const uint32_t base = (uint32_t)__cvta_generic_to_shared(sm);
    const uint32_t sA  = base + (aSel ? OF_AL : 0) + (ar * 24 + ac) * 2;
    const uint32_t sBh = base + OF_BH + (br * 264 + bc) * 2;
    const uint32_t sBl = base + OF_BL + (br * 264 + bc) * 2;

#define LOAD_CHUNK(st, c) do {                                   \
        const int _k0 = (c) * 16;                                \
        const uint32_t _o = (uint32_t)(st) * STG_BYTES;          \
        CP_ASYNC16(sA  + _o, gA  + _k0);                         \
        CP_ASYNC16(sBh + _o, gBh + (size_t)_k0 * 512);           \
        CP_ASYNC16(sBl + _o, gBl + (size_t)_k0 * 512);           \
        CP_COMMIT();                                             \
    } while (0)

    wmma::fragment<wmma::accumulator, 16, 16, 16, float> acc[4][2];
#pragma unroll
    for (int fm = 0; fm < 4; ++fm)
#pragma unroll
        for (int fn = 0; fn < 2; ++fn)
            wmma::fill_fragment(acc[fm][fn], 0.0f);

    LOAD_CHUNK(0, 0);
    LOAD_CHUNK(1, 1);

    for (int c = 0; c < 32; ++c) {
        const int st = c % 3;
        if (c == 31) { CP_WAIT0(); } else { CP_WAIT1(); }
        __syncthreads();

        const __nv_bfloat16* Ah_ = reinterpret_cast<const __nv_bfloat16*>(sm + st * STG_BYTES);
        const __nv_bfloat16* Al_ = reinterpret_cast<const __nv_bfloat16*>(sm + st * STG_BYTES + OF_AL);
        const __nv_bfloat16* Bh_ = reinterpret_cast<const __nv_bfloat16*>(sm + st * STG_BYTES + OF_BH);
        const __nv_bfloat16* Bl_ = reinterpret_cast<const __nv_bfloat16*>(sm + st * STG_BYTES + OF_BL);

        wmma::fragment<wmma::matrix_b, 16, 16, 16, __nv_bfloat16, wmma::row_major> fbh[2], fbl[2];
#pragma unroll
        for (int fn = 0; fn < 2; ++fn) {
            wmma::load_matrix_sync(fbh[fn], Bh_ + wn * 32 + fn * 16, 264);
            wmma::load_matrix_sync(fbl[fn], Bl_ + wn * 32 + fn * 16, 264);
        }
#pragma unroll
        for (int fm = 0; fm < 4; ++fm) {
            wmma::fragment<wmma::matrix_a, 16, 16, 16, __nv_bfloat16, wmma::row_major> fah, fal;
            wmma::load_matrix_sync(fah, Ah_ + (wm * 64 + fm * 16) * 24, 24);
            wmma::load_matrix_sync(fal, Al_ + (wm * 64 + fm * 16) * 24, 24);
#pragma unroll
            for (int fn = 0; fn < 2; ++fn) {
                wmma::mma_sync(acc[fm][fn], fah, fbh[fn], acc[fm][fn]);
                wmma::mma_sync(acc[fm][fn], fah, fbl[fn], acc[fm][fn]);
                wmma::mma_sync(acc[fm][fn], fal, fbh[fn], acc[fm][fn]);
            }
        }
        // Load chunk c+2 into buffer (c+2)%3 == (c-1)%3 — freed by the sync above.
        if (c + 2 < 32) LOAD_CHUNK((c + 2) % 3, c + 2);
    }

#pragma unroll
    for (int fm = 0; fm < 4; ++fm)
#pragma unroll
        for (int fn = 0; fn < 2; ++fn)
            wmma::store_matrix_sync(Cp + (size_t)(wm * 64 + fm * 16) * 512 + wn * 32 + fn * 16,
                                    acc[fm][fn], 512, wmma::mem_row_major);
}

// ===========================================================================
// Inverse: Hermitian spectrum -> real 64, via complex iFFT32 in registers.
// ===========================================================================
__global__ __launch_bounds__(256) void ifft_kernel(float* __restrict__ out)
{
    const int tube = blockIdx.x * 256 + threadIdx.x;
    const int b    = tube >> 16;
    const int in_  = tube & 0xFFFF;

    float zr[32], zi[32];
    const float h = 1.0f / 64.0f;

    {
        const float2 X0  = g_Cf[((size_t)(b * NF + 0)  << 16) + in_];
        const float2 X32 = g_Cf[((size_t)(b * NF + 32) << 16) + in_];
        const float Er = (X0.x + X32.x) * h, Ei = (X0.y + X32.y) * h;
        const float Or = (X0.x - X32.x) * h, Oi = (X0.y - X32.y) * h;
        zr[0] = Er - Oi;
        zi[0] = Ei + Or;
    }
#pragma unroll
    for (int k = 1; k <= 16; ++k) {
        const float2 Xk = g_Cf[((size_t)(b * NF + k)        << 16) + in_];
        const float2 Xq = g_Cf[((size_t)(b * NF + (32 - k)) << 16) + in_];
        const float Er = (Xk.x + Xq.x) * h, Ei = (Xk.y - Xq.y) * h;
        const float Dr = (Xk.x - Xq.x) * h, Di = (Xk.y + Xq.y) * h;
        const float Or = Dr * W64R[k] - Di * W64I[k];
        const float Oi = Dr * W64I[k] + Di * W64R[k];
        zr[k] = Er - Oi;
        zi[k] = Ei + Or;
        if (k < 16) {
            zr[32 - k] = Er + Oi;
            zi[32 - k] = Or - Ei;
        }
    }

    fft32<1>(zr, zi);

    float* dst = out + (size_t)tube * N3;
#pragma unroll
    for (int n = 0; n < 32; n += 2) {
        const int p0 = BR5[n], p1 = BR5[n + 1];
        *reinterpret_cast<float4*>(dst + 2 * n) =
            make_float4(zr[p0], zi[p0], zr[p1], zi[p1]);
    }
}

// ===========================================================================
extern "C" void kernel_launch(void* const* d_in, const int* in_sizes, int n_in,
                              void* d_out, int out_size)
{
    const float* A = (const float*)d_in[0];
    const float* B = (const float*)d_in[1];
    float* out = (float*)d_out;

    cudaFuncSetAttribute(cgemm_wmma_kernel,
                         cudaFuncAttributeMaxDynamicSharedMemorySize, SMEM_GEMM);

    const int fftBlocks = NTUBES / 128;          // 4096
    fft_fwd_kernel<<<fftBlocks, 128>>>(A, 0);
    fft_fwd_kernel<<<fftBlocks, 128>>>(B, 1);

    dim3 ggrid(2, 2, NFP);                       // (m, n, plane-slowest)
    cgemm_wmma_kernel<<<ggrid, 512, SMEM_GEMM>>>();

    ifft_kernel<<<NTUBES / 256, 256>>>(out);
}